// round 13
// baseline (speedup 1.0000x reference)
#include <cuda_runtime.h>
#include <math.h>
#include <stdint.h>

// Problem constants
#define HNUM 256
#define WNUM 256
#define MC   128
#define NSQ  32
#define RR   (NSQ * NSQ)     // 1024
#define TT   512
#define BIN_LEN 0.02f
#define EPS_NORM 1e-12f

// Output layout (all float32, concatenated flattened tuple):
//   origins_out  (MC,RR,3) | directions (MC,RR,3) | t (MC,RR,TT) | xys (MC,RR,2)
#define OFF_ORI 0
#define OFF_DIR (MC * RR * 3)                          // 393216
#define OFF_T   (2 * MC * RR * 3)                      // 786432
#define OFF_XYS (2 * MC * RR * 3 + MC * RR * TT)       // 67895296

#define NTHREADS 1024
#define NBLOCKS  148          // B200/sm_100a SM count; grid-stride is robust anyway
#define NSLABS   (MC * 32)    // 4096 slabs: (m, 32-row chunk), warp-per-row

// Cross-block per-m NaN flags (zero-initialized at module load; fixup resets).
__device__ int g_flag[MC];

__device__ __forceinline__ float norm3(float a, float b, float c) {
    return sqrtf(__fadd_rn(__fadd_rn(__fmul_rn(a, a), __fmul_rn(b, b)), __fmul_rn(c, c)));
}

// ---------------------------------------------------------------------------
// Persistent main kernel: grid = 148 blocks x 1024 threads (all SMs).
//  Prologue (per block): dirs -> shared (12KB); threads 0..127 compute the
//  per-m scalar set (orig, lvec, l, eff, y, x) for ALL m into shared (~5KB).
//  Small outputs: grid-strided coalesced loop over ori|dir|xys (4.6MB).
//  Main: grid-stride over 4096 slabs; slab = (m, chunk); warp w writes row
//  chunk*32+w: broadcast LDS of m-scalars + dirs row, dx/dy chain, then
//  16 elements x R3's exact 15-op sequence + 4x STG.128 (stcs).
//  NaN -> ballot -> global atomicOr(g_flag[m]) (never-taken in practice).
// num/den/dx/dy rounding is op-for-op identical to the reference ordering;
// only the final division is __fdividef (validated: rel_err ~6e-8).
// ---------------------------------------------------------------------------
__global__ void __launch_bounds__(NTHREADS, 1)
fused_kernel(const float* __restrict__ laser_pos,
             const float* __restrict__ camera_pos,
             const float* __restrict__ laser_origin,
             const float* __restrict__ camera_origin,
             const float* __restrict__ dirs,
             const int*   __restrict__ idx_raw,
             float* __restrict__ out) {
    __shared__ float s_dirs[RR * 3];          // 12KB
    __shared__ float s_ox[MC], s_oy[MC], s_oz[MC];
    __shared__ float s_lx[MC], s_ly[MC], s_lz[MC];
    __shared__ float s_l[MC], s_eff[MC], s_yv[MC], s_xv[MC];
    __shared__ int   s_is64;

    const int tid = threadIdx.x;
    const int bid = blockIdx.x;

    // dtype sniff (warp 0): int64 LE => high words of first 32 elems are 0
    if (tid < 32) {
        int hz = (idx_raw[2 * tid + 1] == 0);
        unsigned ball = __ballot_sync(0xffffffffu, hz);
        if (tid == 0) s_is64 = (__popc(ball) >= 2);
    }

    // dirs -> shared
    #pragma unroll
    for (int i = tid; i < RR * 3; i += NTHREADS) s_dirs[i] = __ldg(&dirs[i]);
    __syncthreads();

    // per-m scalars (threads 0..127, one m each)
    if (tid < MC) {
        const int m = tid;
        long long idx = s_is64 ? ((const long long*)idx_raw)[m]
                               : (long long)idx_raw[m];
        int y = (int)(idx / WNUM);
        int x = (int)(idx % WNUM);
        if (m == 0) { y = HNUM / 2; x = WNUM / 2; }

        int base = (y * WNUM + x) * 3;
        float lpx = laser_pos[base + 0], lpy = laser_pos[base + 1], lpz = laser_pos[base + 2];
        float cpx = camera_pos[base + 0], cpy = camera_pos[base + 1], cpz = camera_pos[base + 2];

        float d1 = norm3(__fsub_rn(lpx, laser_origin[0]),
                         __fsub_rn(lpy, laser_origin[1]),
                         __fsub_rn(lpz, laser_origin[2]));
        float d4 = norm3(__fsub_rn(cpx, camera_origin[0]),
                         __fsub_rn(cpy, camera_origin[1]),
                         __fsub_rn(cpz, camera_origin[2]));
        float d1d4 = __fadd_rn(d1, d4);

        float vx = __fsub_rn(lpx, cpx);
        float vy = __fsub_rn(lpy, cpy);
        float vz = __fsub_rn(lpz, cpz);
        float l  = norm3(vx, vy, vz);
        float inv = __fdiv_rn(1.0f, fmaxf(l, EPS_NORM));

        float off_f = ceilf(__fdiv_rn(__fsub_rn(l, d1d4), BIN_LEN));
        int offset = (int)off_f;
        int eff = offset % TT;
        if (eff < 0) eff += TT;

        s_ox[m] = cpx; s_oy[m] = cpy; s_oz[m] = cpz;
        s_lx[m] = __fmul_rn(vx, inv);
        s_ly[m] = __fmul_rn(vy, inv);
        s_lz[m] = __fmul_rn(vz, inv);
        s_l[m] = l; s_eff[m] = (float)eff;
        s_yv[m] = (float)y; s_xv[m] = (float)x;
    }
    __syncthreads();

    // ---- small outputs, grid-strided across all blocks ----
    {
        const int NORI = MC * RR * 3;          // 393216
        const int NXY  = MC * RR * 2;          // 262144
        const int TOTS = 2 * NORI + NXY;
        for (int i = bid * NTHREADS + tid; i < TOTS; i += NBLOCKS * NTHREADS) {
            float v; int o;
            if (i < NORI) {
                int m = i / (RR * 3);
                int c = i % 3;
                v = (c == 0) ? s_ox[m] : (c == 1) ? s_oy[m] : s_oz[m];
                o = OFF_ORI + i;
            } else if (i < 2 * NORI) {
                int e = i - NORI;
                v = s_dirs[e % (RR * 3)];
                o = OFF_DIR + e;
            } else {
                int e = i - 2 * NORI;
                int m = e >> 11;               // / (RR*2)
                v = (e & 1) ? s_xv[m] : s_yv[m];
                o = OFF_XYS + e;
            }
            out[o] = v;
        }
    }

    // ---- t tensor: grid-stride over slabs ----
    const int warp = tid >> 5;
    const int lane = tid & 31;
    float4* tout = (float4*)(out + OFF_T);

    #pragma unroll 1
    for (int s = bid; s < NSLABS; s += NBLOCKS) {
        const int m     = s >> 5;
        const int chunk = s & 31;
        const int r     = chunk * 32 + warp;

        const float lvx = s_lx[m], lvy = s_ly[m], lvz = s_lz[m];
        const float l   = s_l[m];
        const float eff = s_eff[m];
        const float l2  = __fmul_rn(l, l);

        const float d0 = s_dirs[r * 3 + 0];
        const float d1 = s_dirs[r * 3 + 1];
        const float d2 = s_dirs[r * 3 + 2];

        float dx  = __fadd_rn(__fadd_rn(__fmul_rn(d0, lvx), __fmul_rn(d1, lvy)),
                              __fmul_rn(d2, lvz));
        float dx2 = __fmul_rn(dx, dx);
        float dy  = sqrtf(__fsub_rn(1.0f, dx2));   // NaN if dx2 > 1 (propagates)
        float dy2 = __fmul_rn(dy, dy);
        float dxl = __fmul_rn(dx, l);

        float4* trow = tout + ((size_t)m * RR + r) * (TT / 4);
        bool anynan = false;

        #pragma unroll
        for (int j = 0; j < 4; j++) {
            const int i4 = j * 32 + lane;
            float4 v4;
            #pragma unroll
            for (int k = 0; k < 4; k++) {
                float tf   = (float)(i4 * 4 + k);
                float tau  = __fmul_rn(BIN_LEN, fmaxf(tf, eff));
                float tau2 = __fmul_rn(tau, tau);
                float diff = __fsub_rn(tau2, l2);
                float num  = __fmul_rn(__fadd_rn(dxl, tau), diff);
                float den  = __fmul_rn(2.0f,
                               __fadd_rn(__fmul_rn(dx2, diff),
                                         __fmul_rn(dy2, tau2)));
                float v    = __fdividef(num, den);
                anynan |= (v != v);
                ((float*)&v4)[k] = v;
            }
            __stcs(&trow[i4], v4);
        }

        unsigned ball = __ballot_sync(0xffffffffu, anynan);
        if (ball != 0u && lane == 0) atomicOr(&g_flag[m], 1);
    }
}

// ---------------------------------------------------------------------------
// Fixup: grid = MC blocks x 128 threads. Early-exits unless g_flag[m] set
// (never-case for random inputs). Always resets the flag so graph replays
// are deterministic. If set: rewrites m's whole t slice with t_conf.
// ---------------------------------------------------------------------------
__global__ void __launch_bounds__(128)
fixup_kernel(const float* __restrict__ laser_pos,
             const float* __restrict__ camera_pos,
             const float* __restrict__ laser_origin,
             const float* __restrict__ camera_origin,
             const int*   __restrict__ idx_raw,
             float* __restrict__ out) {
    const int m   = blockIdx.x;
    const int tid = threadIdx.x;

    __shared__ int s_f;
    __shared__ float s_d1d4;
    if (tid == 0) {
        s_f = g_flag[m];
        if (s_f) g_flag[m] = 0;               // reset for next replay
    }
    __syncthreads();
    if (!s_f) return;

    if (tid == 0) {
        // dtype sniff (serial here; rare path)
        int zeros = 0;
        #pragma unroll 1
        for (int k = 1; k < 64; k += 2) zeros += (idx_raw[k] == 0);
        int is64 = (zeros >= 2);
        long long idx = is64 ? ((const long long*)idx_raw)[m]
                             : (long long)idx_raw[m];
        int y = (int)(idx / WNUM);
        int x = (int)(idx % WNUM);
        if (m == 0) { y = HNUM / 2; x = WNUM / 2; }
        int base = (y * WNUM + x) * 3;
        float d1 = norm3(__fsub_rn(laser_pos[base + 0], laser_origin[0]),
                         __fsub_rn(laser_pos[base + 1], laser_origin[1]),
                         __fsub_rn(laser_pos[base + 2], laser_origin[2]));
        float d4 = norm3(__fsub_rn(camera_pos[base + 0], camera_origin[0]),
                         __fsub_rn(camera_pos[base + 1], camera_origin[1]),
                         __fsub_rn(camera_pos[base + 2], camera_origin[2]));
        s_d1d4 = __fadd_rn(d1, d4);
    }
    __syncthreads();

    const float d1d4 = s_d1d4;
    const int t0 = tid * 4;
    float4 v4;
    #pragma unroll
    for (int j = 0; j < 4; j++) {
        float tau0 = __fmul_rn((float)(t0 + j), BIN_LEN);
        float d = __fsub_rn(tau0, d1d4);
        if (d <= 0.0f) d = 1e-6f;
        ((float*)&v4)[j] = __fmul_rn(d, 0.5f);
    }
    float4* tbase = (float4*)(out + OFF_T) + (size_t)m * RR * (TT / 4);
    #pragma unroll 1
    for (int r = 0; r < RR; r++) {
        tbase[(size_t)r * (TT / 4) + tid] = v4;
    }
}

// ---------------------------------------------------------------------------
extern "C" void kernel_launch(void* const* d_in, const int* in_sizes, int n_in,
                              void* d_out, int out_size) {
    const float* laser_pos     = (const float*)d_in[0];
    const float* camera_pos    = (const float*)d_in[1];
    const float* laser_origin  = (const float*)d_in[2];
    const float* camera_origin = (const float*)d_in[3];
    const float* directions    = (const float*)d_in[4];
    const int*   idx_raw       = (const int*)d_in[5];
    float* out = (float*)d_out;

    fused_kernel<<<NBLOCKS, NTHREADS>>>(laser_pos, camera_pos, laser_origin,
                                        camera_origin, directions, idx_raw, out);
    fixup_kernel<<<MC, 128>>>(laser_pos, camera_pos, laser_origin,
                              camera_origin, idx_raw, out);
}

// round 14
// speedup vs baseline: 1.0377x; 1.0377x over previous
#include <cuda_runtime.h>
#include <math.h>
#include <stdint.h>

// Problem constants
#define HNUM 256
#define WNUM 256
#define MC   128
#define NSQ  32
#define RR   (NSQ * NSQ)     // 1024
#define TT   512
#define BIN_LEN 0.02f
#define EPS_NORM 1e-12f

// Output layout (all float32, concatenated flattened tuple):
//   origins_out  (MC,RR,3) | directions (MC,RR,3) | t (MC,RR,TT) | xys (MC,RR,2)
#define OFF_ORI 0
#define OFF_DIR (MC * RR * 3)                          // 393216
#define OFF_T   (2 * MC * RR * 3)                      // 786432
#define OFF_XYS (2 * MC * RR * 3 + MC * RR * TT)       // 67895296

#define NTHREADS 1024

__device__ __forceinline__ float norm3(float a, float b, float c) {
    return sqrtf(__fadd_rn(__fadd_rn(__fmul_rn(a, a), __fmul_rn(b, b)), __fmul_rn(c, c)));
}

// ---------------------------------------------------------------------------
// Single fused kernel (Round-3 configuration — measured optimum, 44.5us).
// One block per m (grid=128, 1024 threads, 32 warps).
//  Phase 0: warp 0 computes per-m scalars into shared (incl. idx dtype sniff)
//  Phase A: thread t computes row t's (dx^2, dy^2, dx*l) into s_row (float4)
//  Phase B: warp-per-row (r = rw*32 + warp): per row one broadcast LDS.128,
//           then 16 bins as 4x [4x(tau chain, num, den, fast-div, setp) +
//           STG.128 stcs]. Dense 2KB per-row store regions, fully coalesced.
//  Per-m NaN flag -> in-block rewrite with t_conf (rare path).
// Post-R13 conclusion: the t-store stream is chip-level-bound (~6.1 TB/s
// effective); op-reduction variants (reg/shared tables, 512thr, 148-block
// persistent) all regressed by damaging spill/L1tex/occupancy/launch budget.
// num/den/dx/dy rounding is op-for-op identical to the reference ordering;
// only the final division is __fdividef (validated: rel_err ~6e-8).
// ---------------------------------------------------------------------------
__global__ void __launch_bounds__(NTHREADS, 1)
fused_kernel(const float* __restrict__ laser_pos,
             const float* __restrict__ camera_pos,
             const float* __restrict__ laser_origin,
             const float* __restrict__ camera_origin,
             const float* __restrict__ dirs,
             const int*   __restrict__ idx_raw,
             float* __restrict__ out) {
    __shared__ float4 s_row[RR];              // (dx2, dy2, dxl, 0) per row
    __shared__ float s_orig[3], s_lvec[3];
    __shared__ float s_l, s_eff, s_d1d4, s_y, s_x;
    __shared__ int   s_flag;

    const int m   = blockIdx.x;
    const int tid = threadIdx.x;

    // ---- Phase 0: per-m scalar setup (warp 0) ----
    if (tid < 32) {
        // dtype sniff: int64 little-endian => high words of first 32 elems are 0
        int hz = (idx_raw[2 * tid + 1] == 0);
        unsigned ball = __ballot_sync(0xffffffffu, hz);
        int is64 = (__popc(ball) >= 2);

        if (tid == 0) {
            long long idx = is64 ? ((const long long*)idx_raw)[m]
                                 : (long long)idx_raw[m];
            int y = (int)(idx / WNUM);
            int x = (int)(idx % WNUM);
            if (m == 0) { y = HNUM / 2; x = WNUM / 2; }

            int base = (y * WNUM + x) * 3;
            float lpx = laser_pos[base + 0], lpy = laser_pos[base + 1], lpz = laser_pos[base + 2];
            float cpx = camera_pos[base + 0], cpy = camera_pos[base + 1], cpz = camera_pos[base + 2];

            float d1 = norm3(__fsub_rn(lpx, laser_origin[0]),
                             __fsub_rn(lpy, laser_origin[1]),
                             __fsub_rn(lpz, laser_origin[2]));
            float d4 = norm3(__fsub_rn(cpx, camera_origin[0]),
                             __fsub_rn(cpy, camera_origin[1]),
                             __fsub_rn(cpz, camera_origin[2]));
            float d1d4 = __fadd_rn(d1, d4);

            float vx = __fsub_rn(lpx, cpx);
            float vy = __fsub_rn(lpy, cpy);
            float vz = __fsub_rn(lpz, cpz);
            float l  = norm3(vx, vy, vz);
            float inv = __fdiv_rn(1.0f, fmaxf(l, EPS_NORM));

            float off_f = ceilf(__fdiv_rn(__fsub_rn(l, d1d4), BIN_LEN));
            int offset = (int)off_f;
            int eff = offset % TT;
            if (eff < 0) eff += TT;

            s_orig[0] = cpx; s_orig[1] = cpy; s_orig[2] = cpz;
            s_lvec[0] = __fmul_rn(vx, inv);
            s_lvec[1] = __fmul_rn(vy, inv);
            s_lvec[2] = __fmul_rn(vz, inv);
            s_l = l; s_d1d4 = d1d4; s_eff = (float)eff;
            s_y = (float)y; s_x = (float)x;
            s_flag = 0;
        }
    }
    __syncthreads();

    const float lvx = s_lvec[0], lvy = s_lvec[1], lvz = s_lvec[2];
    const float ox  = s_orig[0], oy  = s_orig[1], oz  = s_orig[2];
    const float l   = s_l;
    const float eff = s_eff;
    const float yv  = s_y, xv = s_x;
    const float l2  = __fmul_rn(l, l);

    // ---- Phase A: per-row (dx2, dy2, dxl) into shared ----
    {
        const int r = tid;
        const float d0 = __ldg(&dirs[r * 3 + 0]);
        const float d1 = __ldg(&dirs[r * 3 + 1]);
        const float d2 = __ldg(&dirs[r * 3 + 2]);
        float dx  = __fadd_rn(__fadd_rn(__fmul_rn(d0, lvx), __fmul_rn(d1, lvy)),
                              __fmul_rn(d2, lvz));
        float dx2 = __fmul_rn(dx, dx);
        float dy  = sqrtf(__fsub_rn(1.0f, dx2));   // NaN if dx2 > 1 (propagates)
        float dy2 = __fmul_rn(dy, dy);
        float dxl = __fmul_rn(dx, l);
        s_row[r] = make_float4(dx2, dy2, dxl, 0.0f);
    }

    // ---- small outputs for this m (coalesced; no sync needed w/ s_row yet) ----
    {
        float* po = out + OFF_ORI + (size_t)m * (RR * 3);
        float* pd = out + OFF_DIR + (size_t)m * (RR * 3);
        #pragma unroll
        for (int i = tid; i < RR * 3; i += NTHREADS) {
            int c = i % 3;
            po[i] = (c == 0) ? ox : (c == 1) ? oy : oz;
            pd[i] = __ldg(&dirs[i]);
        }
        float* pxy = out + OFF_XYS + (size_t)m * (RR * 2);
        #pragma unroll
        for (int i = tid; i < RR * 2; i += NTHREADS) {
            pxy[i] = (i & 1) ? xv : yv;
        }
    }
    __syncthreads();

    // ---- Phase B: t tensor, warp-per-row ----
    const int warp = tid >> 5;
    const int lane = tid & 31;
    bool anynan = false;
    float4* tbase = (float4*)(out + OFF_T) + (size_t)m * RR * (TT / 4);

    #pragma unroll 1
    for (int rw = 0; rw < 32; rw++) {
        const int r = rw * 32 + warp;
        float4 c = s_row[r];                   // broadcast LDS.128
        const float dx2 = c.x, dy2 = c.y, dxl = c.z;

        #pragma unroll
        for (int j = 0; j < 4; j++) {
            const int i4 = j * 32 + lane;
            float4 v4;
            #pragma unroll
            for (int k = 0; k < 4; k++) {
                float tf   = (float)(i4 * 4 + k);
                float tau  = __fmul_rn(BIN_LEN, fmaxf(tf, eff));
                float tau2 = __fmul_rn(tau, tau);
                float diff = __fsub_rn(tau2, l2);
                float num  = __fmul_rn(__fadd_rn(dxl, tau), diff);
                float den  = __fmul_rn(2.0f,
                               __fadd_rn(__fmul_rn(dx2, diff),
                                         __fmul_rn(dy2, tau2)));
                float v    = __fdividef(num, den);
                anynan |= (v != v);
                ((float*)&v4)[k] = v;
            }
            __stcs(&tbase[(size_t)r * (TT / 4) + i4], v4);
        }
    }

    // ---- NaN flag reduce + in-block fixup (rare path) ----
    unsigned ball = __ballot_sync(0xffffffffu, anynan);
    if (ball != 0u && lane == 0) atomicOr(&s_flag, 1);
    __syncthreads();

    if (s_flag) {
        const float d1d4 = s_d1d4;
        float4 c4[4];
        #pragma unroll
        for (int j = 0; j < 4; j++) {
            const int i4 = j * 32 + lane;
            #pragma unroll
            for (int k = 0; k < 4; k++) {
                float tau0 = __fmul_rn((float)(i4 * 4 + k), BIN_LEN);
                float d = __fsub_rn(tau0, d1d4);
                if (d <= 0.0f) d = 1e-6f;
                ((float*)&c4[j])[k] = __fmul_rn(d, 0.5f);
            }
        }
        #pragma unroll 1
        for (int rw = 0; rw < 32; rw++) {
            const int r = rw * 32 + warp;
            #pragma unroll
            for (int j = 0; j < 4; j++) {
                tbase[(size_t)r * (TT / 4) + j * 32 + lane] = c4[j];
            }
        }
    }
}

// ---------------------------------------------------------------------------
extern "C" void kernel_launch(void* const* d_in, const int* in_sizes, int n_in,
                              void* d_out, int out_size) {
    const float* laser_pos     = (const float*)d_in[0];
    const float* camera_pos    = (const float*)d_in[1];
    const float* laser_origin  = (const float*)d_in[2];
    const float* camera_origin = (const float*)d_in[3];
    const float* directions    = (const float*)d_in[4];
    const int*   idx_raw       = (const int*)d_in[5];
    float* out = (float*)d_out;

    fused_kernel<<<MC, NTHREADS>>>(laser_pos, camera_pos, laser_origin,
                                   camera_origin, directions, idx_raw, out);
}

// round 16
// speedup vs baseline: 1.1295x; 1.0885x over previous
#include <cuda_runtime.h>
#include <math.h>
#include <stdint.h>

// Problem constants
#define HNUM 256
#define WNUM 256
#define MC   128
#define NSQ  32
#define RR   (NSQ * NSQ)     // 1024
#define TT   512
#define BIN_LEN 0.02f
#define EPS_NORM 1e-12f

// Output layout (all float32, concatenated flattened tuple):
//   origins_out  (MC,RR,3) | directions (MC,RR,3) | t (MC,RR,TT) | xys (MC,RR,2)
#define OFF_ORI 0
#define OFF_DIR (MC * RR * 3)                          // 393216
#define OFF_T   (2 * MC * RR * 3)                      // 786432
#define OFF_XYS (2 * MC * RR * 3 + MC * RR * TT)       // 67895296

#define NTHREADS 1024

__device__ __forceinline__ float norm3(float a, float b, float c) {
    return sqrtf(__fadd_rn(__fadd_rn(__fmul_rn(a, a), __fmul_rn(b, b)), __fmul_rn(c, c)));
}

// ---------------------------------------------------------------------------
// Single fused kernel (Round-3 configuration — measured optimum; identical
// source has benched 44.5us and 49.2us across broker hosts => ~10% fleet
// noise; all sub-2us micro-ideas are below that floor and unverifiable).
// One block per m (grid=128, 1024 threads, 32 warps).
//  Phase 0: warp 0 computes per-m scalars into shared (incl. idx dtype sniff)
//  Phase A: thread t computes row t's (dx^2, dy^2, dx*l) into s_row (float4)
//  Phase B: warp-per-row (r = rw*32 + warp): per row one broadcast LDS.128,
//           then 16 bins as 4x [4x(tau chain, num, den, fast-div, setp) +
//           STG.128 stcs]. Dense 2KB per-row store regions, fully coalesced.
//  Per-m NaN flag -> in-block rewrite with t_conf (rare path).
// Search summary (all falsified): reg tables @1024thr -> 64-reg spill
// (R5/R6/R11); shared SoA tables -> L1tex contention with the STG stream
// (R8); 512thr + 128-reg budget -> occupancy too low to drive stores (R12);
// 148-block persistent -> chip-level write wall, no per-SM scaling (R13).
// num/den/dx/dy rounding is op-for-op identical to the reference ordering
// (den is the pole-amplified invariant); only the final division is
// __fdividef (validated: rel_err 6.045e-8 on every passing run).
// ---------------------------------------------------------------------------
__global__ void __launch_bounds__(NTHREADS, 1)
fused_kernel(const float* __restrict__ laser_pos,
             const float* __restrict__ camera_pos,
             const float* __restrict__ laser_origin,
             const float* __restrict__ camera_origin,
             const float* __restrict__ dirs,
             const int*   __restrict__ idx_raw,
             float* __restrict__ out) {
    __shared__ float4 s_row[RR];              // (dx2, dy2, dxl, 0) per row
    __shared__ float s_orig[3], s_lvec[3];
    __shared__ float s_l, s_eff, s_d1d4, s_y, s_x;
    __shared__ int   s_flag;

    const int m   = blockIdx.x;
    const int tid = threadIdx.x;

    // ---- Phase 0: per-m scalar setup (warp 0) ----
    if (tid < 32) {
        // dtype sniff: int64 little-endian => high words of first 32 elems are 0
        int hz = (idx_raw[2 * tid + 1] == 0);
        unsigned ball = __ballot_sync(0xffffffffu, hz);
        int is64 = (__popc(ball) >= 2);

        if (tid == 0) {
            long long idx = is64 ? ((const long long*)idx_raw)[m]
                                 : (long long)idx_raw[m];
            int y = (int)(idx / WNUM);
            int x = (int)(idx % WNUM);
            if (m == 0) { y = HNUM / 2; x = WNUM / 2; }

            int base = (y * WNUM + x) * 3;
            float lpx = laser_pos[base + 0], lpy = laser_pos[base + 1], lpz = laser_pos[base + 2];
            float cpx = camera_pos[base + 0], cpy = camera_pos[base + 1], cpz = camera_pos[base + 2];

            float d1 = norm3(__fsub_rn(lpx, laser_origin[0]),
                             __fsub_rn(lpy, laser_origin[1]),
                             __fsub_rn(lpz, laser_origin[2]));
            float d4 = norm3(__fsub_rn(cpx, camera_origin[0]),
                             __fsub_rn(cpy, camera_origin[1]),
                             __fsub_rn(cpz, camera_origin[2]));
            float d1d4 = __fadd_rn(d1, d4);

            float vx = __fsub_rn(lpx, cpx);
            float vy = __fsub_rn(lpy, cpy);
            float vz = __fsub_rn(lpz, cpz);
            float l  = norm3(vx, vy, vz);
            float inv = __fdiv_rn(1.0f, fmaxf(l, EPS_NORM));

            float off_f = ceilf(__fdiv_rn(__fsub_rn(l, d1d4), BIN_LEN));
            int offset = (int)off_f;
            int eff = offset % TT;
            if (eff < 0) eff += TT;

            s_orig[0] = cpx; s_orig[1] = cpy; s_orig[2] = cpz;
            s_lvec[0] = __fmul_rn(vx, inv);
            s_lvec[1] = __fmul_rn(vy, inv);
            s_lvec[2] = __fmul_rn(vz, inv);
            s_l = l; s_d1d4 = d1d4; s_eff = (float)eff;
            s_y = (float)y; s_x = (float)x;
            s_flag = 0;
        }
    }
    __syncthreads();

    const float lvx = s_lvec[0], lvy = s_lvec[1], lvz = s_lvec[2];
    const float ox  = s_orig[0], oy  = s_orig[1], oz  = s_orig[2];
    const float l   = s_l;
    const float eff = s_eff;
    const float yv  = s_y, xv = s_x;
    const float l2  = __fmul_rn(l, l);

    // ---- Phase A: per-row (dx2, dy2, dxl) into shared ----
    {
        const int r = tid;
        const float d0 = __ldg(&dirs[r * 3 + 0]);
        const float d1 = __ldg(&dirs[r * 3 + 1]);
        const float d2 = __ldg(&dirs[r * 3 + 2]);
        float dx  = __fadd_rn(__fadd_rn(__fmul_rn(d0, lvx), __fmul_rn(d1, lvy)),
                              __fmul_rn(d2, lvz));
        float dx2 = __fmul_rn(dx, dx);
        float dy  = sqrtf(__fsub_rn(1.0f, dx2));   // NaN if dx2 > 1 (propagates)
        float dy2 = __fmul_rn(dy, dy);
        float dxl = __fmul_rn(dx, l);
        s_row[r] = make_float4(dx2, dy2, dxl, 0.0f);
    }

    // ---- small outputs for this m (coalesced; no sync needed w/ s_row yet) ----
    {
        float* po = out + OFF_ORI + (size_t)m * (RR * 3);
        float* pd = out + OFF_DIR + (size_t)m * (RR * 3);
        #pragma unroll
        for (int i = tid; i < RR * 3; i += NTHREADS) {
            int c = i % 3;
            po[i] = (c == 0) ? ox : (c == 1) ? oy : oz;
            pd[i] = __ldg(&dirs[i]);
        }
        float* pxy = out + OFF_XYS + (size_t)m * (RR * 2);
        #pragma unroll
        for (int i = tid; i < RR * 2; i += NTHREADS) {
            pxy[i] = (i & 1) ? xv : yv;
        }
    }
    __syncthreads();

    // ---- Phase B: t tensor, warp-per-row ----
    const int warp = tid >> 5;
    const int lane = tid & 31;
    bool anynan = false;
    float4* tbase = (float4*)(out + OFF_T) + (size_t)m * RR * (TT / 4);

    #pragma unroll 1
    for (int rw = 0; rw < 32; rw++) {
        const int r = rw * 32 + warp;
        float4 c = s_row[r];                   // broadcast LDS.128
        const float dx2 = c.x, dy2 = c.y, dxl = c.z;

        #pragma unroll
        for (int j = 0; j < 4; j++) {
            const int i4 = j * 32 + lane;
            float4 v4;
            #pragma unroll
            for (int k = 0; k < 4; k++) {
                float tf   = (float)(i4 * 4 + k);
                float tau  = __fmul_rn(BIN_LEN, fmaxf(tf, eff));
                float tau2 = __fmul_rn(tau, tau);
                float diff = __fsub_rn(tau2, l2);
                float num  = __fmul_rn(__fadd_rn(dxl, tau), diff);
                float den  = __fmul_rn(2.0f,
                               __fadd_rn(__fmul_rn(dx2, diff),
                                         __fmul_rn(dy2, tau2)));
                float v    = __fdividef(num, den);
                anynan |= (v != v);
                ((float*)&v4)[k] = v;
            }
            __stcs(&tbase[(size_t)r * (TT / 4) + i4], v4);
        }
    }

    // ---- NaN flag reduce + in-block fixup (rare path) ----
    unsigned ball = __ballot_sync(0xffffffffu, anynan);
    if (ball != 0u && lane == 0) atomicOr(&s_flag, 1);
    __syncthreads();

    if (s_flag) {
        const float d1d4 = s_d1d4;
        float4 c4[4];
        #pragma unroll
        for (int j = 0; j < 4; j++) {
            const int i4 = j * 32 + lane;
            #pragma unroll
            for (int k = 0; k < 4; k++) {
                float tau0 = __fmul_rn((float)(i4 * 4 + k), BIN_LEN);
                float d = __fsub_rn(tau0, d1d4);
                if (d <= 0.0f) d = 1e-6f;
                ((float*)&c4[j])[k] = __fmul_rn(d, 0.5f);
            }
        }
        #pragma unroll 1
        for (int rw = 0; rw < 32; rw++) {
            const int r = rw * 32 + warp;
            #pragma unroll
            for (int j = 0; j < 4; j++) {
                tbase[(size_t)r * (TT / 4) + j * 32 + lane] = c4[j];
            }
        }
    }
}

// ---------------------------------------------------------------------------
extern "C" void kernel_launch(void* const* d_in, const int* in_sizes, int n_in,
                              void* d_out, int out_size) {
    const float* laser_pos     = (const float*)d_in[0];
    const float* camera_pos    = (const float*)d_in[1];
    const float* laser_origin  = (const float*)d_in[2];
    const float* camera_origin = (const float*)d_in[3];
    const float* directions    = (const float*)d_in[4];
    const int*   idx_raw       = (const int*)d_in[5];
    float* out = (float*)d_out;

    fused_kernel<<<MC, NTHREADS>>>(laser_pos, camera_pos, laser_origin,
                                   camera_origin, directions, idx_raw, out);
}

// round 17
// speedup vs baseline: 1.1303x; 1.0007x over previous
#include <cuda_runtime.h>
#include <math.h>
#include <stdint.h>

// Problem constants
#define HNUM 256
#define WNUM 256
#define MC   128
#define NSQ  32
#define RR   (NSQ * NSQ)     // 1024
#define TT   512
#define BIN_LEN 0.02f
#define EPS_NORM 1e-12f

// Output layout (all float32, concatenated flattened tuple):
//   origins_out  (MC,RR,3) | directions (MC,RR,3) | t (MC,RR,TT) | xys (MC,RR,2)
#define OFF_ORI 0
#define OFF_DIR (MC * RR * 3)                          // 393216
#define OFF_T   (2 * MC * RR * 3)                      // 786432
#define OFF_XYS (2 * MC * RR * 3 + MC * RR * TT)       // 67895296

#define NTHREADS 1024

__device__ __forceinline__ float norm3(float a, float b, float c) {
    return sqrtf(__fadd_rn(__fadd_rn(__fmul_rn(a, a), __fmul_rn(b, b)), __fmul_rn(c, c)));
}

// ---------------------------------------------------------------------------
// Single fused kernel (Round-3 configuration — measured optimum).
// Identical source has benched 44.5 / 49.2 / 45.2 us across broker hosts:
// ~10% fleet noise. Best sample = 6.1 TB/s effective store bandwidth,
// ~93% of the chip-level LTS store ceiling -> at the write wall.
// One block per m (grid=128, 1024 threads, 32 warps).
//  Phase 0: warp 0 computes per-m scalars into shared (incl. idx dtype sniff)
//  Phase A: thread t computes row t's (dx^2, dy^2, dx*l) into s_row (float4)
//  Phase B: warp-per-row (r = rw*32 + warp): per row one broadcast LDS.128,
//           then 16 bins as 4x [4x(tau chain, num, den, fast-div, setp) +
//           STG.128 stcs]. Dense 2KB per-row store regions, fully coalesced.
//  Per-m NaN flag -> in-block rewrite with t_conf (rare path).
// Search summary (all falsified): reg tables @1024thr -> 64-reg spill
// (R5/R6/R11); shared SoA tables -> L1tex contention with the STG stream
// (R8); 512thr + 128-reg budget -> occupancy too low to drive stores (R12);
// 148-block persistent -> chip-level write wall, no per-SM scaling (R13).
// num/den/dx/dy rounding is op-for-op identical to the reference ordering
// (den is the pole-amplified invariant); only the final division is
// __fdividef (validated: rel_err 6.045e-8 on every passing run).
// ---------------------------------------------------------------------------
__global__ void __launch_bounds__(NTHREADS, 1)
fused_kernel(const float* __restrict__ laser_pos,
             const float* __restrict__ camera_pos,
             const float* __restrict__ laser_origin,
             const float* __restrict__ camera_origin,
             const float* __restrict__ dirs,
             const int*   __restrict__ idx_raw,
             float* __restrict__ out) {
    __shared__ float4 s_row[RR];              // (dx2, dy2, dxl, 0) per row
    __shared__ float s_orig[3], s_lvec[3];
    __shared__ float s_l, s_eff, s_d1d4, s_y, s_x;
    __shared__ int   s_flag;

    const int m   = blockIdx.x;
    const int tid = threadIdx.x;

    // ---- Phase 0: per-m scalar setup (warp 0) ----
    if (tid < 32) {
        // dtype sniff: int64 little-endian => high words of first 32 elems are 0
        int hz = (idx_raw[2 * tid + 1] == 0);
        unsigned ball = __ballot_sync(0xffffffffu, hz);
        int is64 = (__popc(ball) >= 2);

        if (tid == 0) {
            long long idx = is64 ? ((const long long*)idx_raw)[m]
                                 : (long long)idx_raw[m];
            int y = (int)(idx / WNUM);
            int x = (int)(idx % WNUM);
            if (m == 0) { y = HNUM / 2; x = WNUM / 2; }

            int base = (y * WNUM + x) * 3;
            float lpx = laser_pos[base + 0], lpy = laser_pos[base + 1], lpz = laser_pos[base + 2];
            float cpx = camera_pos[base + 0], cpy = camera_pos[base + 1], cpz = camera_pos[base + 2];

            float d1 = norm3(__fsub_rn(lpx, laser_origin[0]),
                             __fsub_rn(lpy, laser_origin[1]),
                             __fsub_rn(lpz, laser_origin[2]));
            float d4 = norm3(__fsub_rn(cpx, camera_origin[0]),
                             __fsub_rn(cpy, camera_origin[1]),
                             __fsub_rn(cpz, camera_origin[2]));
            float d1d4 = __fadd_rn(d1, d4);

            float vx = __fsub_rn(lpx, cpx);
            float vy = __fsub_rn(lpy, cpy);
            float vz = __fsub_rn(lpz, cpz);
            float l  = norm3(vx, vy, vz);
            float inv = __fdiv_rn(1.0f, fmaxf(l, EPS_NORM));

            float off_f = ceilf(__fdiv_rn(__fsub_rn(l, d1d4), BIN_LEN));
            int offset = (int)off_f;
            int eff = offset % TT;
            if (eff < 0) eff += TT;

            s_orig[0] = cpx; s_orig[1] = cpy; s_orig[2] = cpz;
            s_lvec[0] = __fmul_rn(vx, inv);
            s_lvec[1] = __fmul_rn(vy, inv);
            s_lvec[2] = __fmul_rn(vz, inv);
            s_l = l; s_d1d4 = d1d4; s_eff = (float)eff;
            s_y = (float)y; s_x = (float)x;
            s_flag = 0;
        }
    }
    __syncthreads();

    const float lvx = s_lvec[0], lvy = s_lvec[1], lvz = s_lvec[2];
    const float ox  = s_orig[0], oy  = s_orig[1], oz  = s_orig[2];
    const float l   = s_l;
    const float eff = s_eff;
    const float yv  = s_y, xv = s_x;
    const float l2  = __fmul_rn(l, l);

    // ---- Phase A: per-row (dx2, dy2, dxl) into shared ----
    {
        const int r = tid;
        const float d0 = __ldg(&dirs[r * 3 + 0]);
        const float d1 = __ldg(&dirs[r * 3 + 1]);
        const float d2 = __ldg(&dirs[r * 3 + 2]);
        float dx  = __fadd_rn(__fadd_rn(__fmul_rn(d0, lvx), __fmul_rn(d1, lvy)),
                              __fmul_rn(d2, lvz));
        float dx2 = __fmul_rn(dx, dx);
        float dy  = sqrtf(__fsub_rn(1.0f, dx2));   // NaN if dx2 > 1 (propagates)
        float dy2 = __fmul_rn(dy, dy);
        float dxl = __fmul_rn(dx, l);
        s_row[r] = make_float4(dx2, dy2, dxl, 0.0f);
    }

    // ---- small outputs for this m (coalesced; no sync needed w/ s_row yet) ----
    {
        float* po = out + OFF_ORI + (size_t)m * (RR * 3);
        float* pd = out + OFF_DIR + (size_t)m * (RR * 3);
        #pragma unroll
        for (int i = tid; i < RR * 3; i += NTHREADS) {
            int c = i % 3;
            po[i] = (c == 0) ? ox : (c == 1) ? oy : oz;
            pd[i] = __ldg(&dirs[i]);
        }
        float* pxy = out + OFF_XYS + (size_t)m * (RR * 2);
        #pragma unroll
        for (int i = tid; i < RR * 2; i += NTHREADS) {
            pxy[i] = (i & 1) ? xv : yv;
        }
    }
    __syncthreads();

    // ---- Phase B: t tensor, warp-per-row ----
    const int warp = tid >> 5;
    const int lane = tid & 31;
    bool anynan = false;
    float4* tbase = (float4*)(out + OFF_T) + (size_t)m * RR * (TT / 4);

    #pragma unroll 1
    for (int rw = 0; rw < 32; rw++) {
        const int r = rw * 32 + warp;
        float4 c = s_row[r];                   // broadcast LDS.128
        const float dx2 = c.x, dy2 = c.y, dxl = c.z;

        #pragma unroll
        for (int j = 0; j < 4; j++) {
            const int i4 = j * 32 + lane;
            float4 v4;
            #pragma unroll
            for (int k = 0; k < 4; k++) {
                float tf   = (float)(i4 * 4 + k);
                float tau  = __fmul_rn(BIN_LEN, fmaxf(tf, eff));
                float tau2 = __fmul_rn(tau, tau);
                float diff = __fsub_rn(tau2, l2);
                float num  = __fmul_rn(__fadd_rn(dxl, tau), diff);
                float den  = __fmul_rn(2.0f,
                               __fadd_rn(__fmul_rn(dx2, diff),
                                         __fmul_rn(dy2, tau2)));
                float v    = __fdividef(num, den);
                anynan |= (v != v);
                ((float*)&v4)[k] = v;
            }
            __stcs(&tbase[(size_t)r * (TT / 4) + i4], v4);
        }
    }

    // ---- NaN flag reduce + in-block fixup (rare path) ----
    unsigned ball = __ballot_sync(0xffffffffu, anynan);
    if (ball != 0u && lane == 0) atomicOr(&s_flag, 1);
    __syncthreads();

    if (s_flag) {
        const float d1d4 = s_d1d4;
        float4 c4[4];
        #pragma unroll
        for (int j = 0; j < 4; j++) {
            const int i4 = j * 32 + lane;
            #pragma unroll
            for (int k = 0; k < 4; k++) {
                float tau0 = __fmul_rn((float)(i4 * 4 + k), BIN_LEN);
                float d = __fsub_rn(tau0, d1d4);
                if (d <= 0.0f) d = 1e-6f;
                ((float*)&c4[j])[k] = __fmul_rn(d, 0.5f);
            }
        }
        #pragma unroll 1
        for (int rw = 0; rw < 32; rw++) {
            const int r = rw * 32 + warp;
            #pragma unroll
            for (int j = 0; j < 4; j++) {
                tbase[(size_t)r * (TT / 4) + j * 32 + lane] = c4[j];
            }
        }
    }
}

// ---------------------------------------------------------------------------
extern "C" void kernel_launch(void* const* d_in, const int* in_sizes, int n_in,
                              void* d_out, int out_size) {
    const float* laser_pos     = (const float*)d_in[0];
    const float* camera_pos    = (const float*)d_in[1];
    const float* laser_origin  = (const float*)d_in[2];
    const float* camera_origin = (const float*)d_in[3];
    const float* directions    = (const float*)d_in[4];
    const int*   idx_raw       = (const int*)d_in[5];
    float* out = (float*)d_out;

    fused_kernel<<<MC, NTHREADS>>>(laser_pos, camera_pos, laser_origin,
                                   camera_origin, directions, idx_raw, out);
}